// round 1
// baseline (speedup 1.0000x reference)
#include <cuda_runtime.h>

// Problem constants (fixed by setup_inputs: x (4, 4096, 2048) f32, dampeners (2, 2048) f32)
namespace {
constexpr int B_DIM  = 4;
constexpr int S_LEN  = 4096;
constexpr int H_DIM  = 2048;
constexpr int CHUNK  = 128;   // time-steps per CTA (must divide S_LEN)
constexpr int TPB    = 128;   // threads per block
constexpr int HPT    = 4;     // channels per thread (float4)
}

// The reference FFT convolution is mathematically exactly the causal IIR scan
//   y[t,h] = g[h]*y[t-1,h] + a[h]*x[t,h],   y[-1]=0
// with a = sigmoid(dampeners[0]), g = (1-a)*sigmoid(dampeners[1]).
//
// Chunked-parallel realization: each CTA owns one (batch, h-slice, time-chunk).
// Since g < 1, the influence of state older than T steps decays as g^T; each
// chunk recomputes a halo of T steps (T derived from g at runtime, clamped to
// the chunk start => falls back to exact full recompute if g -> 1).
__global__ __launch_bounds__(TPB, 8)
void damped_scan_kernel(const float* __restrict__ x,
                        const float* __restrict__ dmp,
                        float* __restrict__ out)
{
    const int b  = blockIdx.z;
    const int t0 = blockIdx.y * CHUNK;
    const int h  = (blockIdx.x * TPB + threadIdx.x) * HPT;

    // Per-channel coefficients (4 channels per thread)
    const float4 d0 = *reinterpret_cast<const float4*>(dmp + h);
    const float4 d1 = *reinterpret_cast<const float4*>(dmp + H_DIM + h);

    const float a0 = 1.f / (1.f + expf(-d0.x));
    const float a1 = 1.f / (1.f + expf(-d0.y));
    const float a2 = 1.f / (1.f + expf(-d0.z));
    const float a3 = 1.f / (1.f + expf(-d0.w));
    const float g0 = (1.f - a0) / (1.f + expf(-d1.x));
    const float g1 = (1.f - a1) / (1.f + expf(-d1.y));
    const float g2 = (1.f - a2) / (1.f + expf(-d1.z));
    const float g3 = (1.f - a3) / (1.f + expf(-d1.w));

    // Halo length: smallest T with gmax^T <= 1e-12 (clamped to chunk start,
    // which also makes chunk 0 exact with T = 0).
    const float gm = fmaxf(fmaxf(g0, g1), fmaxf(g2, g3));
    int T;
    if (!(gm > 0.f)) {
        T = 0;
    } else {
        const float lg = logf(gm);
        if (lg >= -1e-6f) {
            T = t0;                       // g ~ 1: exact full recompute
        } else {
            T = (int)ceilf(27.631021f / (-lg));   // ln(1e12) = 27.631
            if (T > t0) T = t0;
        }
    }

    const size_t cbase = (size_t)b * S_LEN * H_DIM + (size_t)h;
    const float4* xp = reinterpret_cast<const float4*>(
        x + cbase + (size_t)(t0 - T) * H_DIM);
    float4* op = reinterpret_cast<float4*>(
        out + cbase + (size_t)t0 * H_DIM);

    float y0 = 0.f, y1 = 0.f, y2 = 0.f, y3 = 0.f;

    // Halo: warm up the state, no stores.
    for (int t = 0; t < T; ++t) {
        const float4 v = *xp; xp += H_DIM / 4;
        y0 = fmaf(g0, y0, a0 * v.x);
        y1 = fmaf(g1, y1, a1 * v.y);
        y2 = fmaf(g2, y2, a2 * v.z);
        y3 = fmaf(g3, y3, a3 * v.w);
    }

    // Main chunk: stream load -> fma -> store. Loads are independent of the
    // fma chain, so unrolling batches LDG.128s for MLP.
#pragma unroll 8
    for (int t = 0; t < CHUNK; ++t) {
        const float4 v = *xp; xp += H_DIM / 4;
        y0 = fmaf(g0, y0, a0 * v.x);
        y1 = fmaf(g1, y1, a1 * v.y);
        y2 = fmaf(g2, y2, a2 * v.z);
        y3 = fmaf(g3, y3, a3 * v.w);
        float4 w; w.x = y0; w.y = y1; w.z = y2; w.w = y3;
        *op = w; op += H_DIM / 4;
    }
}

extern "C" void kernel_launch(void* const* d_in, const int* in_sizes, int n_in,
                              void* d_out, int out_size)
{
    const float* x   = (const float*)d_in[0];
    const float* dmp = (const float*)d_in[1];
    float* out       = (float*)d_out;

    dim3 grid(H_DIM / (TPB * HPT),   // 4  h-groups
              S_LEN / CHUNK,         // 32 time-chunks
              B_DIM);                // 4  batches
    damped_scan_kernel<<<grid, TPB>>>(x, dmp, out);
}